// round 5
// baseline (speedup 1.0000x reference)
#include <cuda_runtime.h>

#define BB 4
#define SS 2048
#define HH 1024
#define NROWS (BB*SS)

// Scratch (static device globals; no allocation)
__device__ float g_VL[(size_t)NROWS * HH];  // value_layer [B*S, H]
__device__ float g_a[NROWS];                // (X@U)/8 per row
__device__ float g_b[NROWS];                // X@V^T per row

// ---------------------------------------------------------------------------
// Kernel 1: a[row] = (hs[row]·U[0:H] + U[H]) / 8 ;  b[row] = hs[row]·V[0:H] + V[H]
// One block (256 threads) per row; each thread handles one float4 of the row.
// ---------------------------------------------------------------------------
__global__ void __launch_bounds__(256) rank1_kernel(
    const float* __restrict__ hs, const float* __restrict__ U,
    const float* __restrict__ V)
{
    const int row = blockIdx.x;
    const int tid = threadIdx.x;
    const float4 h = ((const float4*)(hs + (size_t)row * HH))[tid];
    const float4 u = ((const float4*)U)[tid];
    const float4 v = ((const float4*)V)[tid];
    float su = h.x * u.x + h.y * u.y + h.z * u.z + h.w * u.w;
    float sv = h.x * v.x + h.y * v.y + h.z * v.z + h.w * v.w;
    #pragma unroll
    for (int o = 16; o > 0; o >>= 1) {
        su += __shfl_xor_sync(0xffffffffu, su, o);
        sv += __shfl_xor_sync(0xffffffffu, sv, o);
    }
    __shared__ float s_u[8], s_v[8];
    if ((tid & 31) == 0) { s_u[tid >> 5] = su; s_v[tid >> 5] = sv; }
    __syncthreads();
    if (tid == 0) {
        float tu = 0.f, tv = 0.f;
        #pragma unroll
        for (int i = 0; i < 8; i++) { tu += s_u[i]; tv += s_v[i]; }
        g_a[row] = (tu + U[HH]) * 0.125f;  // fold 1/sqrt(64)
        g_b[row] = tv + V[HH];
    }
}

// ---------------------------------------------------------------------------
// Kernel 2: value_layer = hs @ W^T + bias   (C[i,j] = sum_k A[i,k]*W[j,k])
// Classic fp32 SGEMM, NT form. BM=BN=128, BK=8, 256 threads, 8x8 per thread.
// ---------------------------------------------------------------------------
__global__ void __launch_bounds__(256) vproj_kernel(
    const float* __restrict__ A, const float* __restrict__ W,
    const float* __restrict__ bias)
{
    __shared__ float As[8][128];
    __shared__ float Ws[8][128];

    const int bm = blockIdx.y * 128;
    const int bn = blockIdx.x * 128;
    const int tid = threadIdx.x;
    const int tx = tid & 15;          // 0..15 -> n
    const int ty = tid >> 4;          // 0..15 -> m
    const int lrow = tid >> 1;        // 0..127 tile row to load
    const int lk4  = (tid & 1) * 4;   // 0 or 4

    const float* Ag = A + (size_t)(bm + lrow) * HH + lk4;
    const float* Wg = W + (size_t)(bn + lrow) * HH + lk4;

    float acc[8][8];
    #pragma unroll
    for (int i = 0; i < 8; i++)
        #pragma unroll
        for (int j = 0; j < 8; j++) acc[i][j] = 0.f;

    for (int k0 = 0; k0 < HH; k0 += 8) {
        const float4 av = *(const float4*)(Ag + k0);
        const float4 wv = *(const float4*)(Wg + k0);
        As[lk4 + 0][lrow] = av.x; As[lk4 + 1][lrow] = av.y;
        As[lk4 + 2][lrow] = av.z; As[lk4 + 3][lrow] = av.w;
        Ws[lk4 + 0][lrow] = wv.x; Ws[lk4 + 1][lrow] = wv.y;
        Ws[lk4 + 2][lrow] = wv.z; Ws[lk4 + 3][lrow] = wv.w;
        __syncthreads();
        #pragma unroll
        for (int k = 0; k < 8; k++) {
            float a[8], b[8];
            *(float4*)(a)     = *(const float4*)&As[k][ty * 8];
            *(float4*)(a + 4) = *(const float4*)&As[k][ty * 8 + 4];
            *(float4*)(b)     = *(const float4*)&Ws[k][tx * 8];
            *(float4*)(b + 4) = *(const float4*)&Ws[k][tx * 8 + 4];
            #pragma unroll
            for (int i = 0; i < 8; i++)
                #pragma unroll
                for (int j = 0; j < 8; j++)
                    acc[i][j] = fmaf(a[i], b[j], acc[i][j]);
        }
        __syncthreads();
    }

    float bsv[8];
    *(float4*)(bsv)     = *(const float4*)(bias + bn + tx * 8);
    *(float4*)(bsv + 4) = *(const float4*)(bias + bn + tx * 8 + 4);

    #pragma unroll
    for (int i = 0; i < 8; i++) {
        float* cp = g_VL + (size_t)(bm + ty * 8 + i) * HH + bn + tx * 8;
        float4 o0, o1;
        o0.x = acc[i][0] + bsv[0]; o0.y = acc[i][1] + bsv[1];
        o0.z = acc[i][2] + bsv[2]; o0.w = acc[i][3] + bsv[3];
        o1.x = acc[i][4] + bsv[4]; o1.y = acc[i][5] + bsv[5];
        o1.z = acc[i][6] + bsv[6]; o1.w = acc[i][7] + bsv[7];
        ((float4*)cp)[0] = o0;
        ((float4*)cp)[1] = o1;
    }
}

// ---------------------------------------------------------------------------
// Kernel 3: sparse softmax + gather.
// scores[s,t] = a_s*b_t + m_t. Only t with score >= max-40 matter
// (dropped mass <= 2048*e^-40 ~ 1e-14 relative; fp32 reference underflows
// them anyway). One block (128 threads) per output row s.
// ---------------------------------------------------------------------------
__global__ void __launch_bounds__(128) attn_kernel(
    const float* __restrict__ mask, float* __restrict__ out)
{
    const int row   = blockIdx.x;
    const int batch = row >> 11;
    const int tid   = threadIdx.x;
    const int lane  = tid & 31;
    const int wid   = tid >> 5;

    const float* bb = g_b + (batch << 11);
    const float* mm = mask + (batch << 11);
    const float  a  = g_a[row];

    __shared__ float s_red[4];
    __shared__ int   s_cnt4[4];
    __shared__ int   s_t[SS];
    __shared__ float s_w[SS];

    // Pass 1: row max of z_t = a*b_t + m_t
    float lmax = -3.4e38f;
    #pragma unroll
    for (int c = 0; c < 16; c++) {
        int t = c * 128 + tid;
        lmax = fmaxf(lmax, fmaf(a, bb[t], mm[t]));
    }
    #pragma unroll
    for (int o = 16; o > 0; o >>= 1)
        lmax = fmaxf(lmax, __shfl_xor_sync(0xffffffffu, lmax, o));
    if (lane == 0) s_red[wid] = lmax;
    __syncthreads();
    const float gmax = fmaxf(fmaxf(s_red[0], s_red[1]),
                             fmaxf(s_red[2], s_red[3]));
    const float thr = gmax - 40.f;

    // Pass 2: deterministic ordered compaction of active t, weights, sum
    int count = 0;
    float lsum = 0.f;
    for (int c = 0; c < 16; c++) {
        int t = c * 128 + tid;
        float z = fmaf(a, bb[t], mm[t]);
        bool act = (z >= thr);
        unsigned m = __ballot_sync(0xffffffffu, act);
        if (lane == 0) s_cnt4[wid] = __popc(m);
        __syncthreads();
        int off = count;
        #pragma unroll
        for (int ww = 0; ww < 4; ww++)
            if (ww < wid) off += s_cnt4[ww];
        int tot = s_cnt4[0] + s_cnt4[1] + s_cnt4[2] + s_cnt4[3];
        off += __popc(m & ((1u << lane) - 1u));
        if (act) {
            float w = expf(z - gmax);
            lsum += w;
            s_t[off] = t;
            s_w[off] = w;
        }
        count += tot;
        __syncthreads();
    }
    #pragma unroll
    for (int o = 16; o > 0; o >>= 1)
        lsum += __shfl_xor_sync(0xffffffffu, lsum, o);
    if (lane == 0) s_red[wid] = lsum;
    __syncthreads();
    const float tsum = s_red[0] + s_red[1] + s_red[2] + s_red[3];

    // Gather: ctx[h] = sum_i w_i * VL[t_i, h]; thread owns 8 h-columns
    float acc0 = 0.f, acc1 = 0.f, acc2 = 0.f, acc3 = 0.f;
    float acc4 = 0.f, acc5 = 0.f, acc6 = 0.f, acc7 = 0.f;
    const int h0 = tid * 8;
    const float* vbase = g_VL + ((size_t)(batch << 11)) * HH + h0;
    for (int i = 0; i < count; i++) {
        int t = s_t[i];
        float w = s_w[i];
        const float4* v = (const float4*)(vbase + (size_t)t * HH);
        float4 v0 = v[0], v1 = v[1];
        acc0 = fmaf(w, v0.x, acc0); acc1 = fmaf(w, v0.y, acc1);
        acc2 = fmaf(w, v0.z, acc2); acc3 = fmaf(w, v0.w, acc3);
        acc4 = fmaf(w, v1.x, acc4); acc5 = fmaf(w, v1.y, acc5);
        acc6 = fmaf(w, v1.z, acc6); acc7 = fmaf(w, v1.w, acc7);
    }
    const float inv = 1.f / tsum;
    float4 o0, o1;
    o0.x = acc0 * inv; o0.y = acc1 * inv; o0.z = acc2 * inv; o0.w = acc3 * inv;
    o1.x = acc4 * inv; o1.y = acc5 * inv; o1.z = acc6 * inv; o1.w = acc7 * inv;
    float4* op = (float4*)(out + (size_t)row * HH + h0);
    op[0] = o0;
    op[1] = o1;
}

// ---------------------------------------------------------------------------
extern "C" void kernel_launch(void* const* d_in, const int* in_sizes, int n_in,
                              void* d_out, int out_size)
{
    const float* hs      = (const float*)d_in[0];  // [4,2048,1024]
    const float* mask    = (const float*)d_in[1];  // [4,2048]
    const float* value_w = (const float*)d_in[2];  // [1024,1024]
    const float* value_b = (const float*)d_in[3];  // [1024]
    const float* U       = (const float*)d_in[4];  // [1025,1]
    const float* V       = (const float*)d_in[5];  // [1,1025]
    float* out = (float*)d_out;

    rank1_kernel<<<NROWS, 256>>>(hs, U, V);

    dim3 grid2(HH / 128, NROWS / 128);
    vproj_kernel<<<grid2, 256>>>(hs, value_w, value_b);

    attn_kernel<<<NROWS, 128>>>(mask, out);
}

// round 11
// speedup vs baseline: 1.9692x; 1.9692x over previous
#include <cuda_runtime.h>
#include <cuda_bf16.h>
#include <cstdint>

#define BB 4
#define SS 2048
#define HH 1024
#define NROWS (BB*SS)

// Scratch (static device globals; no allocation)
__device__ __align__(256) float g_VL[(size_t)NROWS * HH];  // value_layer [B*S, H]
__device__ float g_a[NROWS];                               // (X@U)/8 per row
__device__ float g_b[NROWS];                               // X@V^T per row
__device__ __align__(256) __nv_bfloat16 g_Ah[(size_t)NROWS * HH];
__device__ __align__(256) __nv_bfloat16 g_Al[(size_t)NROWS * HH];
__device__ __align__(256) __nv_bfloat16 g_Wh[(size_t)HH * HH];
__device__ __align__(256) __nv_bfloat16 g_Wl[(size_t)HH * HH];

// ---------------------------------------------------------------------------
// Portable (sm_80+) helpers: cp.async, ldmatrix, mma.sync bf16
// ---------------------------------------------------------------------------
__device__ __forceinline__ uint32_t smem_u32(const void* p) {
    uint32_t a;
    asm("{ .reg .u64 t; cvta.to.shared.u64 t, %1; cvt.u32.u64 %0, t; }"
        : "=r"(a) : "l"(p));
    return a;
}

__device__ __forceinline__ void cp16(uint32_t dst, const void* src) {
    asm volatile("cp.async.cg.shared.global [%0], [%1], 16;"
                 :: "r"(dst), "l"(src) : "memory");
}

__device__ __forceinline__ void ldsm_x4(uint32_t& r0, uint32_t& r1,
                                        uint32_t& r2, uint32_t& r3,
                                        uint32_t addr) {
    asm volatile("ldmatrix.sync.aligned.m8n8.x4.shared.b16 {%0,%1,%2,%3}, [%4];"
                 : "=r"(r0), "=r"(r1), "=r"(r2), "=r"(r3) : "r"(addr) : "memory");
}

__device__ __forceinline__ void mma_bf16(float* c, const uint32_t* a,
                                         const uint32_t* b) {
    asm volatile(
        "mma.sync.aligned.m16n8k16.row.col.f32.bf16.bf16.f32 "
        "{%0,%1,%2,%3}, {%4,%5,%6,%7}, {%8,%9}, {%0,%1,%2,%3};"
        : "+f"(c[0]), "+f"(c[1]), "+f"(c[2]), "+f"(c[3])
        : "r"(a[0]), "r"(a[1]), "r"(a[2]), "r"(a[3]), "r"(b[0]), "r"(b[1]));
}

__device__ __forceinline__ uint32_t swz128(uint32_t off) {
    return off ^ ((off >> 3) & 0x70);
}

// ---------------------------------------------------------------------------
// Kernel 1: rank-1 vectors + fused hi/lo bf16 split of hs.
// ---------------------------------------------------------------------------
__global__ void __launch_bounds__(256) rank1_kernel(
    const float* __restrict__ hs, const float* __restrict__ U,
    const float* __restrict__ V)
{
    const int row = blockIdx.x;
    const int tid = threadIdx.x;
    const float4 h = ((const float4*)(hs + (size_t)row * HH))[tid];

    __nv_bfloat16 h0 = __float2bfloat16(h.x);
    __nv_bfloat16 h1 = __float2bfloat16(h.y);
    __nv_bfloat16 h2 = __float2bfloat16(h.z);
    __nv_bfloat16 h3 = __float2bfloat16(h.w);
    __nv_bfloat16 l0 = __float2bfloat16(h.x - __bfloat162float(h0));
    __nv_bfloat16 l1 = __float2bfloat16(h.y - __bfloat162float(h1));
    __nv_bfloat16 l2 = __float2bfloat16(h.z - __bfloat162float(h2));
    __nv_bfloat16 l3 = __float2bfloat16(h.w - __bfloat162float(h3));
    __nv_bfloat162* ph = (__nv_bfloat162*)(g_Ah + (size_t)row * HH + tid * 4);
    __nv_bfloat162* pl = (__nv_bfloat162*)(g_Al + (size_t)row * HH + tid * 4);
    ph[0] = __halves2bfloat162(h0, h1);
    ph[1] = __halves2bfloat162(h2, h3);
    pl[0] = __halves2bfloat162(l0, l1);
    pl[1] = __halves2bfloat162(l2, l3);

    const float4 u = ((const float4*)U)[tid];
    const float4 v = ((const float4*)V)[tid];
    float su = h.x * u.x + h.y * u.y + h.z * u.z + h.w * u.w;
    float sv = h.x * v.x + h.y * v.y + h.z * v.z + h.w * v.w;
    #pragma unroll
    for (int o = 16; o > 0; o >>= 1) {
        su += __shfl_xor_sync(0xffffffffu, su, o);
        sv += __shfl_xor_sync(0xffffffffu, sv, o);
    }
    __shared__ float s_u[8], s_v[8];
    if ((tid & 31) == 0) { s_u[tid >> 5] = su; s_v[tid >> 5] = sv; }
    __syncthreads();
    if (tid == 0) {
        float tu = 0.f, tv = 0.f;
        #pragma unroll
        for (int i = 0; i < 8; i++) { tu += s_u[i]; tv += s_v[i]; }
        g_a[row] = (tu + U[HH]) * 0.125f;  // fold 1/sqrt(64)
        g_b[row] = tv + V[HH];
    }
}

// ---------------------------------------------------------------------------
// Kernel 1b: hi/lo bf16 split of value_w (1024x1024)
// ---------------------------------------------------------------------------
__global__ void __launch_bounds__(256) wconv_kernel(const float* __restrict__ w)
{
    const int idx = blockIdx.x * 256 + threadIdx.x;
    const float4 x = ((const float4*)w)[idx];
    __nv_bfloat16 h0 = __float2bfloat16(x.x);
    __nv_bfloat16 h1 = __float2bfloat16(x.y);
    __nv_bfloat16 h2 = __float2bfloat16(x.z);
    __nv_bfloat16 h3 = __float2bfloat16(x.w);
    __nv_bfloat16 l0 = __float2bfloat16(x.x - __bfloat162float(h0));
    __nv_bfloat16 l1 = __float2bfloat16(x.y - __bfloat162float(h1));
    __nv_bfloat16 l2 = __float2bfloat16(x.z - __bfloat162float(h2));
    __nv_bfloat16 l3 = __float2bfloat16(x.w - __bfloat162float(h3));
    __nv_bfloat162* ph = (__nv_bfloat162*)(g_Wh + (size_t)idx * 4);
    __nv_bfloat162* pl = (__nv_bfloat162*)(g_Wl + (size_t)idx * 4);
    ph[0] = __halves2bfloat162(h0, h1);
    ph[1] = __halves2bfloat162(h2, h3);
    pl[0] = __halves2bfloat162(l0, l1);
    pl[1] = __halves2bfloat162(l2, l3);
}

// ---------------------------------------------------------------------------
// Kernel 2: value projection = bf16x3 split GEMM via mma.sync (HMMA path).
// C[i,j] = sum_k A[i,k]*W[j,k] + bias[j]; products AhWh + AhWl + AlWh.
// CTA 128x128, 256 thr (8 warps 2x4, warp 64x32), BK=64, 2-stage cp.async.
// SMEM tiles: 128 rows x 128B, SW128 swizzled. k-step address update is XOR
// (swz128(off+k) == swz128(off) ^ k when off bits5-6 are clear) — NOT add.
// ---------------------------------------------------------------------------
#define AH_OFF 0
#define AL_OFF 16384
#define WH_OFF 32768
#define WL_OFF 49152
#define STAGE_BYTES 65536
#define GEMM_SMEM_TOTAL (2 * STAGE_BYTES)

__device__ __forceinline__ void load_slab(uint32_t sb, int bm, int bn, int k0,
                                          int tid)
{
    const char* a_h = (const char*)g_Ah + (size_t)bm * 2048 + k0 * 2;
    const char* a_l = (const char*)g_Al + (size_t)bm * 2048 + k0 * 2;
    const char* w_h = (const char*)g_Wh + (size_t)bn * 2048 + k0 * 2;
    const char* w_l = (const char*)g_Wl + (size_t)bn * 2048 + k0 * 2;
    #pragma unroll
    for (int i = 0; i < 4; i++) {
        int cid = tid + i * 256;                  // 0..1023
        int row = cid >> 3;                       // 0..127
        int c16 = (cid & 7) * 16;                 // byte within 128B row
        uint32_t swz = swz128((uint32_t)(row * 128 + c16));
        size_t goff = (size_t)row * 2048 + c16;
        cp16(sb + AH_OFF + swz, a_h + goff);
        cp16(sb + AL_OFF + swz, a_l + goff);
        cp16(sb + WH_OFF + swz, w_h + goff);
        cp16(sb + WL_OFF + swz, w_l + goff);
    }
}

__global__ void __launch_bounds__(256, 1)
gemm_kernel(const float* __restrict__ bias)
{
    extern __shared__ char smem[];
    const uint32_t smem_base = smem_u32(smem);
    const int tid  = threadIdx.x;
    const int wid  = tid >> 5;
    const int lane = tid & 31;

    const int bm = (blockIdx.x >> 3) * 128;   // M tile
    const int bn = (blockIdx.x & 7) * 128;    // N tile

    const int warp_m = (wid & 1) * 64;
    const int warp_n = (wid >> 1) * 32;

    const uint32_t st0 = smem_base;
    const uint32_t st1 = smem_base + STAGE_BYTES;

    float acc[4][4][4];
    #pragma unroll
    for (int i = 0; i < 4; i++)
        #pragma unroll
        for (int j = 0; j < 4; j++)
            #pragma unroll
            for (int q = 0; q < 4; q++) acc[i][j][q] = 0.f;

    // Swizzled per-lane ldmatrix base offsets (k-chunk 0). Per k-step ks the
    // address is base ^ (ks*32): ks*32 touches only bits 5-6, which are clear
    // in the pre-swizzle offset, so XOR after swizzle is exact.
    // A x4: lanes0-15 rows m0-15 kbyte0, lanes16-31 rows m0-15 kbyte16
    //   -> regs = (m0-7,k0-7),(m8-15,k0-7),(m0-7,k8-15),(m8-15,k8-15) = a0..a3
    uint32_t a_base[4];
    #pragma unroll
    for (int mf = 0; mf < 4; mf++)
        a_base[mf] = swz128((uint32_t)(
            (warp_m + mf * 16 + (lane & 15)) * 128 + ((lane >> 4) & 1) * 16));
    // B x4: lanes0-7 (n0-7,k0-7); 8-15 (n0-7,k8-15); 16-23 (n8-15,k0-7);
    //       24-31 (n8-15,k8-15) -> r0,r1 = nfrag0 b0,b1; r2,r3 = nfrag1
    uint32_t b_base[2];
    #pragma unroll
    for (int p = 0; p < 2; p++)
        b_base[p] = swz128((uint32_t)(
            (warp_n + p * 16 + (lane & 7) + ((lane & 16) >> 1)) * 128
            + ((lane & 8) ? 16u : 0u)));

    // Prologue
    load_slab(st0, bm, bn, 0, tid);
    asm volatile("cp.async.commit_group;" ::: "memory");
    load_slab(st1, bm, bn, 64, tid);
    asm volatile("cp.async.commit_group;" ::: "memory");

    for (int j = 0; j < 16; j++) {
        const uint32_t sb = (j & 1) ? st1 : st0;
        if (j < 15) asm volatile("cp.async.wait_group 1;" ::: "memory");
        else        asm volatile("cp.async.wait_group 0;" ::: "memory");
        __syncthreads();

        #pragma unroll
        for (int ks = 0; ks < 4; ks++) {
            const uint32_t kso = (uint32_t)(ks * 32);
            uint32_t af[4][4], bh[4][2], bl[4][2];
            #pragma unroll
            for (int mf = 0; mf < 4; mf++)
                ldsm_x4(af[mf][0], af[mf][1], af[mf][2], af[mf][3],
                        sb + AH_OFF + (a_base[mf] ^ kso));
            #pragma unroll
            for (int p = 0; p < 2; p++)
                ldsm_x4(bh[2*p][0], bh[2*p][1], bh[2*p+1][0], bh[2*p+1][1],
                        sb + WH_OFF + (b_base[p] ^ kso));
            #pragma unroll
            for (int mf = 0; mf < 4; mf++)
                #pragma unroll
                for (int nf = 0; nf < 4; nf++)
                    mma_bf16(acc[mf][nf], af[mf], bh[nf]);
            #pragma unroll
            for (int p = 0; p < 2; p++)
                ldsm_x4(bl[2*p][0], bl[2*p][1], bl[2*p+1][0], bl[2*p+1][1],
                        sb + WL_OFF + (b_base[p] ^ kso));
            #pragma unroll
            for (int mf = 0; mf < 4; mf++)
                #pragma unroll
                for (int nf = 0; nf < 4; nf++)
                    mma_bf16(acc[mf][nf], af[mf], bl[nf]);
            #pragma unroll
            for (int mf = 0; mf < 4; mf++)
                ldsm_x4(af[mf][0], af[mf][1], af[mf][2], af[mf][3],
                        sb + AL_OFF + (a_base[mf] ^ kso));
            #pragma unroll
            for (int mf = 0; mf < 4; mf++)
                #pragma unroll
                for (int nf = 0; nf < 4; nf++)
                    mma_bf16(acc[mf][nf], af[mf], bh[nf]);
        }

        __syncthreads();   // all warps done reading stage before overwrite
        if (j + 2 < 16) {
            load_slab(sb, bm, bn, (j + 2) * 64, tid);
            asm volatile("cp.async.commit_group;" ::: "memory");
        }
    }

    // Epilogue: add bias, write fp32 to g_VL.
    // C fragment: c0,c1 at (row=lane>>2, col=2*(lane&3)); c2,c3 at row+8.
    const int r0 = bm + warp_m + (lane >> 2);
    const int c0 = bn + warp_n + 2 * (lane & 3);
    #pragma unroll
    for (int nf = 0; nf < 4; nf++) {
        const int c = c0 + nf * 8;
        const float b0 = bias[c], b1 = bias[c + 1];
        #pragma unroll
        for (int mf = 0; mf < 4; mf++) {
            const int r = r0 + mf * 16;
            float2 v0 = { acc[mf][nf][0] + b0, acc[mf][nf][1] + b1 };
            float2 v1 = { acc[mf][nf][2] + b0, acc[mf][nf][3] + b1 };
            *(float2*)(g_VL + (size_t)r * HH + c)       = v0;
            *(float2*)(g_VL + (size_t)(r + 8) * HH + c) = v1;
        }
    }
}

// ---------------------------------------------------------------------------
// Kernel 3: sparse softmax + gather (unchanged from passing version).
// ---------------------------------------------------------------------------
__global__ void __launch_bounds__(128) attn_kernel(
    const float* __restrict__ mask, float* __restrict__ out)
{
    const int row   = blockIdx.x;
    const int batch = row >> 11;
    const int tid   = threadIdx.x;
    const int lane  = tid & 31;
    const int wid   = tid >> 5;

    const float* bb = g_b + (batch << 11);
    const float* mm = mask + (batch << 11);
    const float  a  = g_a[row];

    __shared__ float s_red[4];
    __shared__ int   s_cnt4[4];
    __shared__ int   s_t[SS];
    __shared__ float s_w[SS];

    float lmax = -3.4e38f;
    #pragma unroll
    for (int c = 0; c < 16; c++) {
        int t = c * 128 + tid;
        lmax = fmaxf(lmax, fmaf(a, bb[t], mm[t]));
    }
    #pragma unroll
    for (int o = 16; o > 0; o >>= 1)
        lmax = fmaxf(lmax, __shfl_xor_sync(0xffffffffu, lmax, o));
    if (lane == 0) s_red[wid] = lmax;
    __syncthreads();
    const float gmax = fmaxf(fmaxf(s_red[0], s_red[1]),
                             fmaxf(s_red[2], s_red[3]));
    const float thr = gmax - 40.f;

    int count = 0;
    float lsum = 0.f;
    for (int c = 0; c < 16; c++) {
        int t = c * 128 + tid;
        float z = fmaf(a, bb[t], mm[t]);
        bool act = (z >= thr);
        unsigned m = __ballot_sync(0xffffffffu, act);
        if (lane == 0) s_cnt4[wid] = __popc(m);
        __syncthreads();
        int off = count;
        #pragma unroll
        for (int ww = 0; ww < 4; ww++)
            if (ww < wid) off += s_cnt4[ww];
        int tot = s_cnt4[0] + s_cnt4[1] + s_cnt4[2] + s_cnt4[3];
        off += __popc(m & ((1u << lane) - 1u));
        if (act) {
            float w = expf(z - gmax);
            lsum += w;
            s_t[off] = t;
            s_w[off] = w;
        }
        count += tot;
        __syncthreads();
    }
    #pragma unroll
    for (int o = 16; o > 0; o >>= 1)
        lsum += __shfl_xor_sync(0xffffffffu, lsum, o);
    if (lane == 0) s_red[wid] = lsum;
    __syncthreads();
    const float tsum = s_red[0] + s_red[1] + s_red[2] + s_red[3];

    float acc0 = 0.f, acc1 = 0.f, acc2 = 0.f, acc3 = 0.f;
    float acc4 = 0.f, acc5 = 0.f, acc6 = 0.f, acc7 = 0.f;
    const int h0 = tid * 8;
    const float* vbase = g_VL + ((size_t)(batch << 11)) * HH + h0;
    for (int i = 0; i < count; i++) {
        int t = s_t[i];
        float w = s_w[i];
        const float4* v = (const float4*)(vbase + (size_t)t * HH);
        float4 v0 = v[0], v1 = v[1];
        acc0 = fmaf(w, v0.x, acc0); acc1 = fmaf(w, v0.y, acc1);
        acc2 = fmaf(w, v0.z, acc2); acc3 = fmaf(w, v0.w, acc3);
        acc4 = fmaf(w, v1.x, acc4); acc5 = fmaf(w, v1.y, acc5);
        acc6 = fmaf(w, v1.z, acc6); acc7 = fmaf(w, v1.w, acc7);
    }
    const float inv = 1.f / tsum;
    float4 o0, o1;
    o0.x = acc0 * inv; o0.y = acc1 * inv; o0.z = acc2 * inv; o0.w = acc3 * inv;
    o1.x = acc4 * inv; o1.y = acc5 * inv; o1.z = acc6 * inv; o1.w = acc7 * inv;
    float4* op = (float4*)(out + (size_t)row * HH + h0);
    op[0] = o0;
    op[1] = o1;
}

// ---------------------------------------------------------------------------
extern "C" void kernel_launch(void* const* d_in, const int* in_sizes, int n_in,
                              void* d_out, int out_size)
{
    const float* hs      = (const float*)d_in[0];  // [4,2048,1024]
    const float* mask    = (const float*)d_in[1];  // [4,2048]
    const float* value_w = (const float*)d_in[2];  // [1024,1024]
    const float* value_b = (const float*)d_in[3];  // [1024]
    const float* U       = (const float*)d_in[4];  // [1025,1]
    const float* V       = (const float*)d_in[5];  // [1,1025]
    float* out = (float*)d_out;

    static bool attr_set = false;
    if (!attr_set) {
        cudaFuncSetAttribute(gemm_kernel,
                             cudaFuncAttributeMaxDynamicSharedMemorySize,
                             GEMM_SMEM_TOTAL);
        attr_set = true;
    }

    rank1_kernel<<<NROWS, 256>>>(hs, U, V);               // + hs hi/lo split
    wconv_kernel<<<HH * HH / 4 / 256, 256>>>(value_w);    // W hi/lo split
    gemm_kernel<<<(NROWS / 128) * (HH / 128), 256, GEMM_SMEM_TOTAL>>>(value_b);
    attn_kernel<<<NROWS, 128>>>(mask, out);
}

// round 12
// speedup vs baseline: 1.9999x; 1.0156x over previous
#include <cuda_runtime.h>
#include <cuda_bf16.h>
#include <cstdint>

#define BB 4
#define SS 2048
#define HH 1024
#define NROWS (BB*SS)

// Scratch (static device globals; no allocation)
__device__ __align__(256) float g_VL[(size_t)NROWS * HH];  // value_layer [B*S, H]
__device__ float g_a[NROWS];                               // (X@U)/8 per row
__device__ float g_b[NROWS];                               // X@V^T per row
__device__ __align__(256) __nv_bfloat16 g_Ah[(size_t)NROWS * HH];
__device__ __align__(256) __nv_bfloat16 g_Al[(size_t)NROWS * HH];
__device__ __align__(256) __nv_bfloat16 g_Wh[(size_t)HH * HH];
__device__ __align__(256) __nv_bfloat16 g_Wl[(size_t)HH * HH];

// ---------------------------------------------------------------------------
// Portable (sm_80+) helpers: cp.async, ldmatrix, mma.sync bf16
// ---------------------------------------------------------------------------
__device__ __forceinline__ uint32_t smem_u32(const void* p) {
    uint32_t a;
    asm("{ .reg .u64 t; cvta.to.shared.u64 t, %1; cvt.u32.u64 %0, t; }"
        : "=r"(a) : "l"(p));
    return a;
}

__device__ __forceinline__ void cp16(uint32_t dst, const void* src) {
    asm volatile("cp.async.cg.shared.global [%0], [%1], 16;"
                 :: "r"(dst), "l"(src) : "memory");
}

__device__ __forceinline__ void ldsm_x4(uint32_t& r0, uint32_t& r1,
                                        uint32_t& r2, uint32_t& r3,
                                        uint32_t addr) {
    asm volatile("ldmatrix.sync.aligned.m8n8.x4.shared.b16 {%0,%1,%2,%3}, [%4];"
                 : "=r"(r0), "=r"(r1), "=r"(r2), "=r"(r3) : "r"(addr) : "memory");
}

__device__ __forceinline__ void mma_bf16(float* c, const uint32_t* a,
                                         const uint32_t* b) {
    asm volatile(
        "mma.sync.aligned.m16n8k16.row.col.f32.bf16.bf16.f32 "
        "{%0,%1,%2,%3}, {%4,%5,%6,%7}, {%8,%9}, {%0,%1,%2,%3};"
        : "+f"(c[0]), "+f"(c[1]), "+f"(c[2]), "+f"(c[3])
        : "r"(a[0]), "r"(a[1]), "r"(a[2]), "r"(a[3]), "r"(b[0]), "r"(b[1]));
}

__device__ __forceinline__ uint32_t swz128(uint32_t off) {
    return off ^ ((off >> 3) & 0x70);
}

// ---------------------------------------------------------------------------
// Kernel 1: rank-1 vectors + fused hi/lo bf16 split of hs.
// ---------------------------------------------------------------------------
__global__ void __launch_bounds__(256) rank1_kernel(
    const float* __restrict__ hs, const float* __restrict__ U,
    const float* __restrict__ V)
{
    const int row = blockIdx.x;
    const int tid = threadIdx.x;
    const float4 h = ((const float4*)(hs + (size_t)row * HH))[tid];

    __nv_bfloat16 h0 = __float2bfloat16(h.x);
    __nv_bfloat16 h1 = __float2bfloat16(h.y);
    __nv_bfloat16 h2 = __float2bfloat16(h.z);
    __nv_bfloat16 h3 = __float2bfloat16(h.w);
    __nv_bfloat16 l0 = __float2bfloat16(h.x - __bfloat162float(h0));
    __nv_bfloat16 l1 = __float2bfloat16(h.y - __bfloat162float(h1));
    __nv_bfloat16 l2 = __float2bfloat16(h.z - __bfloat162float(h2));
    __nv_bfloat16 l3 = __float2bfloat16(h.w - __bfloat162float(h3));
    __nv_bfloat162* ph = (__nv_bfloat162*)(g_Ah + (size_t)row * HH + tid * 4);
    __nv_bfloat162* pl = (__nv_bfloat162*)(g_Al + (size_t)row * HH + tid * 4);
    ph[0] = __halves2bfloat162(h0, h1);
    ph[1] = __halves2bfloat162(h2, h3);
    pl[0] = __halves2bfloat162(l0, l1);
    pl[1] = __halves2bfloat162(l2, l3);

    const float4 u = ((const float4*)U)[tid];
    const float4 v = ((const float4*)V)[tid];
    float su = h.x * u.x + h.y * u.y + h.z * u.z + h.w * u.w;
    float sv = h.x * v.x + h.y * v.y + h.z * v.z + h.w * v.w;
    #pragma unroll
    for (int o = 16; o > 0; o >>= 1) {
        su += __shfl_xor_sync(0xffffffffu, su, o);
        sv += __shfl_xor_sync(0xffffffffu, sv, o);
    }
    __shared__ float s_u[8], s_v[8];
    if ((tid & 31) == 0) { s_u[tid >> 5] = su; s_v[tid >> 5] = sv; }
    __syncthreads();
    if (tid == 0) {
        float tu = 0.f, tv = 0.f;
        #pragma unroll
        for (int i = 0; i < 8; i++) { tu += s_u[i]; tv += s_v[i]; }
        g_a[row] = (tu + U[HH]) * 0.125f;  // fold 1/sqrt(64)
        g_b[row] = tv + V[HH];
    }
}

// ---------------------------------------------------------------------------
// Kernel 1b: hi/lo bf16 split of value_w (1024x1024)
// ---------------------------------------------------------------------------
__global__ void __launch_bounds__(256) wconv_kernel(const float* __restrict__ w)
{
    const int idx = blockIdx.x * 256 + threadIdx.x;
    const float4 x = ((const float4*)w)[idx];
    __nv_bfloat16 h0 = __float2bfloat16(x.x);
    __nv_bfloat16 h1 = __float2bfloat16(x.y);
    __nv_bfloat16 h2 = __float2bfloat16(x.z);
    __nv_bfloat16 h3 = __float2bfloat16(x.w);
    __nv_bfloat16 l0 = __float2bfloat16(x.x - __bfloat162float(h0));
    __nv_bfloat16 l1 = __float2bfloat16(x.y - __bfloat162float(h1));
    __nv_bfloat16 l2 = __float2bfloat16(x.z - __bfloat162float(h2));
    __nv_bfloat16 l3 = __float2bfloat16(x.w - __bfloat162float(h3));
    __nv_bfloat162* ph = (__nv_bfloat162*)(g_Wh + (size_t)idx * 4);
    __nv_bfloat162* pl = (__nv_bfloat162*)(g_Wl + (size_t)idx * 4);
    ph[0] = __halves2bfloat162(h0, h1);
    ph[1] = __halves2bfloat162(h2, h3);
    pl[0] = __halves2bfloat162(l0, l1);
    pl[1] = __halves2bfloat162(l2, l3);
}

// ---------------------------------------------------------------------------
// Kernel 2: value projection = bf16x3 split GEMM via mma.sync (HMMA path).
// C[i,j] = sum_k A[i,k]*W[j,k] + bias[j]; products AhWh + AhWl + AlWh.
// CTA 128x128, 256 thr (8 warps 2x4, warp 64x32), BK=64, 2-stage cp.async.
// SMEM tiles: 128 rows x 128B, SW128 swizzled. k-step address update is XOR
// (swz128(off+k) == swz128(off) ^ k when off bits5-6 are clear) — NOT add.
// ---------------------------------------------------------------------------
#define AH_OFF 0
#define AL_OFF 16384
#define WH_OFF 32768
#define WL_OFF 49152
#define STAGE_BYTES 65536
#define GEMM_SMEM_TOTAL (2 * STAGE_BYTES)

__device__ __forceinline__ void load_slab(uint32_t sb, int bm, int bn, int k0,
                                          int tid)
{
    const char* a_h = (const char*)g_Ah + (size_t)bm * 2048 + k0 * 2;
    const char* a_l = (const char*)g_Al + (size_t)bm * 2048 + k0 * 2;
    const char* w_h = (const char*)g_Wh + (size_t)bn * 2048 + k0 * 2;
    const char* w_l = (const char*)g_Wl + (size_t)bn * 2048 + k0 * 2;
    #pragma unroll
    for (int i = 0; i < 4; i++) {
        int cid = tid + i * 256;                  // 0..1023
        int row = cid >> 3;                       // 0..127
        int c16 = (cid & 7) * 16;                 // byte within 128B row
        uint32_t swz = swz128((uint32_t)(row * 128 + c16));
        size_t goff = (size_t)row * 2048 + c16;
        cp16(sb + AH_OFF + swz, a_h + goff);
        cp16(sb + AL_OFF + swz, a_l + goff);
        cp16(sb + WH_OFF + swz, w_h + goff);
        cp16(sb + WL_OFF + swz, w_l + goff);
    }
}

__global__ void __launch_bounds__(256, 1)
gemm_kernel(const float* __restrict__ bias)
{
    extern __shared__ char smem[];
    const uint32_t smem_base = smem_u32(smem);
    const int tid  = threadIdx.x;
    const int wid  = tid >> 5;
    const int lane = tid & 31;

    const int bm = (blockIdx.x >> 3) * 128;   // M tile
    const int bn = (blockIdx.x & 7) * 128;    // N tile

    const int warp_m = (wid & 1) * 64;
    const int warp_n = (wid >> 1) * 32;

    const uint32_t st0 = smem_base;
    const uint32_t st1 = smem_base + STAGE_BYTES;

    float acc[4][4][4];
    #pragma unroll
    for (int i = 0; i < 4; i++)
        #pragma unroll
        for (int j = 0; j < 4; j++)
            #pragma unroll
            for (int q = 0; q < 4; q++) acc[i][j][q] = 0.f;

    // Swizzled per-lane ldmatrix base offsets (k-chunk 0). Per k-step ks the
    // address is base ^ (ks*32): ks*32 touches only bits 5-6, which are clear
    // in the pre-swizzle offset, so XOR after swizzle is exact.
    // A x4: lanes0-15 rows m0-15 kbyte0, lanes16-31 rows m0-15 kbyte16
    //   -> regs = (m0-7,k0-7),(m8-15,k0-7),(m0-7,k8-15),(m8-15,k8-15) = a0..a3
    uint32_t a_base[4];
    #pragma unroll
    for (int mf = 0; mf < 4; mf++)
        a_base[mf] = swz128((uint32_t)(
            (warp_m + mf * 16 + (lane & 15)) * 128 + ((lane >> 4) & 1) * 16));
    // B x4: lanes0-7 (n0-7,k0-7); 8-15 (n0-7,k8-15); 16-23 (n8-15,k0-7);
    //       24-31 (n8-15,k8-15) -> r0,r1 = nfrag0 b0,b1; r2,r3 = nfrag1
    uint32_t b_base[2];
    #pragma unroll
    for (int p = 0; p < 2; p++)
        b_base[p] = swz128((uint32_t)(
            (warp_n + p * 16 + (lane & 7) + ((lane & 16) >> 1)) * 128
            + ((lane & 8) ? 16u : 0u)));

    // Prologue
    load_slab(st0, bm, bn, 0, tid);
    asm volatile("cp.async.commit_group;" ::: "memory");
    load_slab(st1, bm, bn, 64, tid);
    asm volatile("cp.async.commit_group;" ::: "memory");

    for (int j = 0; j < 16; j++) {
        const uint32_t sb = (j & 1) ? st1 : st0;
        if (j < 15) asm volatile("cp.async.wait_group 1;" ::: "memory");
        else        asm volatile("cp.async.wait_group 0;" ::: "memory");
        __syncthreads();

        #pragma unroll
        for (int ks = 0; ks < 4; ks++) {
            const uint32_t kso = (uint32_t)(ks * 32);
            uint32_t af[4][4], bh[4][2], bl[4][2];
            #pragma unroll
            for (int mf = 0; mf < 4; mf++)
                ldsm_x4(af[mf][0], af[mf][1], af[mf][2], af[mf][3],
                        sb + AH_OFF + (a_base[mf] ^ kso));
            #pragma unroll
            for (int p = 0; p < 2; p++)
                ldsm_x4(bh[2*p][0], bh[2*p][1], bh[2*p+1][0], bh[2*p+1][1],
                        sb + WH_OFF + (b_base[p] ^ kso));
            #pragma unroll
            for (int mf = 0; mf < 4; mf++)
                #pragma unroll
                for (int nf = 0; nf < 4; nf++)
                    mma_bf16(acc[mf][nf], af[mf], bh[nf]);
            #pragma unroll
            for (int p = 0; p < 2; p++)
                ldsm_x4(bl[2*p][0], bl[2*p][1], bl[2*p+1][0], bl[2*p+1][1],
                        sb + WL_OFF + (b_base[p] ^ kso));
            #pragma unroll
            for (int mf = 0; mf < 4; mf++)
                #pragma unroll
                for (int nf = 0; nf < 4; nf++)
                    mma_bf16(acc[mf][nf], af[mf], bl[nf]);
            #pragma unroll
            for (int mf = 0; mf < 4; mf++)
                ldsm_x4(af[mf][0], af[mf][1], af[mf][2], af[mf][3],
                        sb + AL_OFF + (a_base[mf] ^ kso));
            #pragma unroll
            for (int mf = 0; mf < 4; mf++)
                #pragma unroll
                for (int nf = 0; nf < 4; nf++)
                    mma_bf16(acc[mf][nf], af[mf], bh[nf]);
        }

        __syncthreads();   // all warps done reading stage before overwrite
        if (j + 2 < 16) {
            load_slab(sb, bm, bn, (j + 2) * 64, tid);
            asm volatile("cp.async.commit_group;" ::: "memory");
        }
    }

    // Epilogue: add bias, write fp32 to g_VL.
    // C fragment: c0,c1 at (row=lane>>2, col=2*(lane&3)); c2,c3 at row+8.
    const int r0 = bm + warp_m + (lane >> 2);
    const int c0 = bn + warp_n + 2 * (lane & 3);
    #pragma unroll
    for (int nf = 0; nf < 4; nf++) {
        const int c = c0 + nf * 8;
        const float b0 = bias[c], b1 = bias[c + 1];
        #pragma unroll
        for (int mf = 0; mf < 4; mf++) {
            const int r = r0 + mf * 16;
            float2 v0 = { acc[mf][nf][0] + b0, acc[mf][nf][1] + b1 };
            float2 v1 = { acc[mf][nf][2] + b0, acc[mf][nf][3] + b1 };
            *(float2*)(g_VL + (size_t)r * HH + c)       = v0;
            *(float2*)(g_VL + (size_t)(r + 8) * HH + c) = v1;
        }
    }
}

// ---------------------------------------------------------------------------
// Kernel 3: sparse softmax + gather (unchanged from passing version).
// ---------------------------------------------------------------------------
__global__ void __launch_bounds__(128) attn_kernel(
    const float* __restrict__ mask, float* __restrict__ out)
{
    const int row   = blockIdx.x;
    const int batch = row >> 11;
    const int tid   = threadIdx.x;
    const int lane  = tid & 31;
    const int wid   = tid >> 5;

    const float* bb = g_b + (batch << 11);
    const float* mm = mask + (batch << 11);
    const float  a  = g_a[row];

    __shared__ float s_red[4];
    __shared__ int   s_cnt4[4];
    __shared__ int   s_t[SS];
    __shared__ float s_w[SS];

    float lmax = -3.4e38f;
    #pragma unroll
    for (int c = 0; c < 16; c++) {
        int t = c * 128 + tid;
        lmax = fmaxf(lmax, fmaf(a, bb[t], mm[t]));
    }
    #pragma unroll
    for (int o = 16; o > 0; o >>= 1)
        lmax = fmaxf(lmax, __shfl_xor_sync(0xffffffffu, lmax, o));
    if (lane == 0) s_red[wid] = lmax;
    __syncthreads();
    const float gmax = fmaxf(fmaxf(s_red[0], s_red[1]),
                             fmaxf(s_red[2], s_red[3]));
    const float thr = gmax - 40.f;

    int count = 0;
    float lsum = 0.f;
    for (int c = 0; c < 16; c++) {
        int t = c * 128 + tid;
        float z = fmaf(a, bb[t], mm[t]);
        bool act = (z >= thr);
        unsigned m = __ballot_sync(0xffffffffu, act);
        if (lane == 0) s_cnt4[wid] = __popc(m);
        __syncthreads();
        int off = count;
        #pragma unroll
        for (int ww = 0; ww < 4; ww++)
            if (ww < wid) off += s_cnt4[ww];
        int tot = s_cnt4[0] + s_cnt4[1] + s_cnt4[2] + s_cnt4[3];
        off += __popc(m & ((1u << lane) - 1u));
        if (act) {
            float w = expf(z - gmax);
            lsum += w;
            s_t[off] = t;
            s_w[off] = w;
        }
        count += tot;
        __syncthreads();
    }
    #pragma unroll
    for (int o = 16; o > 0; o >>= 1)
        lsum += __shfl_xor_sync(0xffffffffu, lsum, o);
    if (lane == 0) s_red[wid] = lsum;
    __syncthreads();
    const float tsum = s_red[0] + s_red[1] + s_red[2] + s_red[3];

    float acc0 = 0.f, acc1 = 0.f, acc2 = 0.f, acc3 = 0.f;
    float acc4 = 0.f, acc5 = 0.f, acc6 = 0.f, acc7 = 0.f;
    const int h0 = tid * 8;
    const float* vbase = g_VL + ((size_t)(batch << 11)) * HH + h0;
    for (int i = 0; i < count; i++) {
        int t = s_t[i];
        float w = s_w[i];
        const float4* v = (const float4*)(vbase + (size_t)t * HH);
        float4 v0 = v[0], v1 = v[1];
        acc0 = fmaf(w, v0.x, acc0); acc1 = fmaf(w, v0.y, acc1);
        acc2 = fmaf(w, v0.z, acc2); acc3 = fmaf(w, v0.w, acc3);
        acc4 = fmaf(w, v1.x, acc4); acc5 = fmaf(w, v1.y, acc5);
        acc6 = fmaf(w, v1.z, acc6); acc7 = fmaf(w, v1.w, acc7);
    }
    const float inv = 1.f / tsum;
    float4 o0, o1;
    o0.x = acc0 * inv; o0.y = acc1 * inv; o0.z = acc2 * inv; o0.w = acc3 * inv;
    o1.x = acc4 * inv; o1.y = acc5 * inv; o1.z = acc6 * inv; o1.w = acc7 * inv;
    float4* op = (float4*)(out + (size_t)row * HH + h0);
    op[0] = o0;
    op[1] = o1;
}

// ---------------------------------------------------------------------------
extern "C" void kernel_launch(void* const* d_in, const int* in_sizes, int n_in,
                              void* d_out, int out_size)
{
    const float* hs      = (const float*)d_in[0];  // [4,2048,1024]
    const float* mask    = (const float*)d_in[1];  // [4,2048]
    const float* value_w = (const float*)d_in[2];  // [1024,1024]
    const float* value_b = (const float*)d_in[3];  // [1024]
    const float* U       = (const float*)d_in[4];  // [1025,1]
    const float* V       = (const float*)d_in[5];  // [1,1025]
    float* out = (float*)d_out;

    static bool attr_set = false;
    if (!attr_set) {
        cudaFuncSetAttribute(gemm_kernel,
                             cudaFuncAttributeMaxDynamicSharedMemorySize,
                             GEMM_SMEM_TOTAL);
        attr_set = true;
    }

    rank1_kernel<<<NROWS, 256>>>(hs, U, V);               // + hs hi/lo split
    wconv_kernel<<<HH * HH / 4 / 256, 256>>>(value_w);    // W hi/lo split
    gemm_kernel<<<(NROWS / 128) * (HH / 128), 256, GEMM_SMEM_TOTAL>>>(value_b);
    attn_kernel<<<NROWS, 128>>>(mask, out);
}